// round 6
// baseline (speedup 1.0000x reference)
#include <cuda_runtime.h>

// CharRNN on GB300 — R6.
//  - prep: EWe = embedding @ W_e (kills the input GEMM; per-step xw is a lookup)
//  - rnn: 128 CTAs x 800 threads (25 warps, 2x occupancy vs R5).
//    Thread (j, q): output column j (0..199), K-quarter q (0..3), both batch rows.
//    W_h quarter-column in registers: 25 fma.rn.f32x2 pairs (50 regs) -> fits
//    the 64K regfile at 800 threads.
//    Reduction across quarters via shfl_xor (q = lane bits 0-1): no pmat smem,
//    ONE __syncthreads per step (was two).
//    h stored quarter-padded (stride 52) so quarter bases stay 16B-aligned and
//    the 4-distinct-address warp LDS is bank-conflict-free.
//    Logits (h @ W_o) fused: 264 threads, double-buffered partials, the gmem
//    store deferred one step so it needs no extra barrier.

#define H     200
#define NROW  2
#define SEQ   1024
#define VOCAB 33
#define BATCH 256
#define QPAD  52            // padded quarter stride (floats), 16B-aligned
#define NTHR  800

__device__ float g_EWe[VOCAB * H];

union U64 {
    unsigned long long u;
    float2 f;
};

__device__ __forceinline__ void ffma2(U64 &acc, U64 a, U64 b) {
    asm("fma.rn.f32x2 %0, %1, %2, %0;" : "+l"(acc.u) : "l"(a.u), "l"(b.u));
}

__device__ __forceinline__ float fast_tanh(float v) {
    v = fminf(15.f, fmaxf(-15.f, v));
    float e = __expf(2.f * v);
    return __fdividef(e - 1.f, e + 1.f);
}

// EWe[v][j] = sum_e emb[v][e] * We[e][j].
__global__ void prep_kernel(const float* __restrict__ emb,
                            const float* __restrict__ We) {
    int v = blockIdx.x;
    int j = threadIdx.x;
    float acc = 0.f;
    #pragma unroll 4
    for (int e = 0; e < H; e++)
        acc = fmaf(emb[v * H + e], We[e * H + j], acc);
    g_EWe[v * H + j] = acc;
}

__global__ void __launch_bounds__(NTHR, 1) rnn_kernel(
    const int* __restrict__ x, const float* __restrict__ h0,
    const float* __restrict__ Wh, const float* __restrict__ Wo,
    float* __restrict__ out, int out_elems)
{
    __shared__ float  hbuf[2][NROW][4 * QPAD];   // quarter-padded hidden, dbl-buf
    __shared__ float  lpart[2][NROW][VOCAB][4];  // logits partials, dbl-buf
    __shared__ int    tok[NROW][SEQ];
    __shared__ float2 WoT[VOCAB][H / 2];         // W_o^T, K-paired

    const int tid = threadIdx.x;
    const int b0  = blockIdx.x * NROW;
    const int j   = tid >> 2;     // output column 0..199
    const int q   = tid & 3;      // K-quarter 0..3 (lane bits 0-1)

    // ---- preload tokens / WoT / initial hidden (padded) ----
    for (int idx = tid; idx < NROW * SEQ; idx += NTHR) {
        int r = idx >> 10, t = idx & (SEQ - 1);
        tok[r][t] = x[(b0 + r) * SEQ + t];
    }
    for (int idx = tid; idx < VOCAB * (H / 2); idx += NTHR) {
        int v = idx / (H / 2), m = idx % (H / 2);
        WoT[v][m] = make_float2(Wo[(2 * m) * VOCAB + v],
                                Wo[(2 * m + 1) * VOCAB + v]);
    }
    for (int idx = tid; idx < NROW * H; idx += NTHR) {
        int r = idx / H, jj = idx - r * H;
        int qq = jj / 50;
        hbuf[0][r][qq * QPAD + (jj - 50 * qq)] = h0[(b0 + r) * H + jj];
    }

    // ---- W_h quarter-column -> 25 packed pairs in registers ----
    U64 w[25];
    #pragma unroll
    for (int m = 0; m < 25; m++) {
        int i0 = 50 * q + 2 * m;
        w[m].f.x = Wh[i0 * H + j];
        w[m].f.y = Wh[(i0 + 1) * H + j];
    }

    // h-writer location for this thread's column
    const int wq   = j / 50;
    const int woff = wq * QPAD + (j - 50 * wq);

    // logits role: columns j<66 (all quarters) -> (row, vocab, quarter)
    const bool do_log = (j < 2 * VOCAB);
    const int  lr = j & 1, lv = j >> 1, lq = q;
    // output role: tid<66 -> (row, vocab)
    const bool do_out = (tid < NROW * VOCAB);
    const int  orow = tid & 1, ov = tid >> 1;

    const int xrow = (q < 2) ? q : 0;   // q=0 -> row0 xw, q=1 -> row1 xw

    __syncthreads();

    int cur = 0;
    for (int t = 0; t < SEQ; t++) {
        const int pb = t & 1;           // lpart write buffer this step

        // xw prefetch (L1-resident 26KB table)
        float xw = g_EWe[tok[xrow][t] * H + j];

        // deferred output store: logits(t-2) from lpart[(t-1)&1]
        if (t >= 2 && do_out) {
            const float* lp = lpart[pb ^ 1][orow][ov];
            out[((long long)(b0 + orow) * SEQ + (t - 2)) * VOCAB + ov]
                = lp[0] + lp[1] + lp[2] + lp[3];
        }

        // fused logits partials for h_{t-1} (= hbuf[cur])
        if (do_log) {
            U64 la, lb; la.u = lb.u = 0ull;
            const float2* hl = (const float2*)&hbuf[cur][lr][QPAD * lq];
            #pragma unroll
            for (int m = 0; m < 25; m++) {
                U64 hv; hv.f = hl[m];
                U64 wv; wv.f = WoT[lv][lq * 25 + m];
                if (m & 1) ffma2(lb, hv, wv); else ffma2(la, hv, wv);
            }
            lpart[pb][lr][lv][lq] = la.f.x + la.f.y + lb.f.x + lb.f.y;
        }

        // matvec: quarter-q partial of (h_{t-1} @ W_h)[r][j], both rows
        const float4* a0 = (const float4*)&hbuf[cur][0][QPAD * q];
        const float4* a1 = (const float4*)&hbuf[cur][1][QPAD * q];
        U64 c0a, c0b, c1a, c1b;
        c0a.u = c0b.u = c1a.u = c1b.u = 0ull;
        #pragma unroll
        for (int m4 = 0; m4 < 12; m4++) {
            float4 v0 = a0[m4];    // 4 distinct 16B addrs per warp: conflict-free
            float4 v1 = a1[m4];
            U64 p0, p1, p2, p3;
            p0.f = make_float2(v0.x, v0.y);
            p1.f = make_float2(v0.z, v0.w);
            p2.f = make_float2(v1.x, v1.y);
            p3.f = make_float2(v1.z, v1.w);
            ffma2(c0a, p0, w[2 * m4]);
            ffma2(c0b, p1, w[2 * m4 + 1]);
            ffma2(c1a, p2, w[2 * m4]);
            ffma2(c1b, p3, w[2 * m4 + 1]);
        }
        {   // tail pair (floats 48..49 of the quarter)
            U64 t0, t1;
            t0.f = ((const float2*)a0)[24];
            t1.f = ((const float2*)a1)[24];
            ffma2(c0a, t0, w[24]);
            ffma2(c1a, t1, w[24]);
        }
        float y0 = c0a.f.x + c0a.f.y + c0b.f.x + c0b.f.y;
        float y1 = c1a.f.x + c1a.f.y + c1b.f.x + c1b.f.y;

        // butterfly reduce across quarters (lane bits 0-1)
        y0 += __shfl_xor_sync(0xFFFFFFFFu, y0, 1);
        y0 += __shfl_xor_sync(0xFFFFFFFFu, y0, 2);
        y1 += __shfl_xor_sync(0xFFFFFFFFu, y1, 1);
        y1 += __shfl_xor_sync(0xFFFFFFFFu, y1, 2);

        const int nxt = cur ^ 1;
        if (q == 0) hbuf[nxt][0][woff] = fast_tanh(xw + y0);
        if (q == 1) hbuf[nxt][1][woff] = fast_tanh(xw + y1);

        __syncthreads();
        cur = nxt;
    }

    // ---- epilogue ----
    // logits(SEQ-2) sits in lpart[(SEQ-1)&1]
    if (do_out) {
        const float* lp = lpart[(SEQ - 1) & 1][orow][ov];
        out[((long long)(b0 + orow) * SEQ + (SEQ - 2)) * VOCAB + ov]
            = lp[0] + lp[1] + lp[2] + lp[3];
    }
    // logits(SEQ-1) from hbuf[cur]
    if (do_log) {
        U64 la, lb; la.u = lb.u = 0ull;
        const float2* hl = (const float2*)&hbuf[cur][lr][QPAD * lq];
        #pragma unroll
        for (int m = 0; m < 25; m++) {
            U64 hv; hv.f = hl[m];
            U64 wv; wv.f = WoT[lv][lq * 25 + m];
            if (m & 1) ffma2(lb, hv, wv); else ffma2(la, hv, wv);
        }
        lpart[0][lr][lv][lq] = la.f.x + la.f.y + lb.f.x + lb.f.y;
    }
    __syncthreads();
    if (do_out) {
        const float* lp = lpart[0][orow][ov];
        out[((long long)(b0 + orow) * SEQ + (SEQ - 1)) * VOCAB + ov]
            = lp[0] + lp[1] + lp[2] + lp[3];
    }

    // final hidden (second output, if present in d_out)
    long long base = (long long)BATCH * SEQ * VOCAB;
    if ((long long)out_elems >= base + (long long)BATCH * H) {
        for (int idx = tid; idx < NROW * H; idx += NTHR) {
            int r = idx / H, jj = idx - r * H;
            int qq = jj / 50;
            out[base + (long long)(b0 + r) * H + jj]
                = hbuf[cur][r][qq * QPAD + (jj - 50 * qq)];
        }
    }
}

extern "C" void kernel_launch(void* const* d_in, const int* in_sizes, int n_in,
                              void* d_out, int out_size) {
    // metadata order: x(int32), hidden, embedding, W_e, W_h, W_o
    const int*   x      = (const int*)d_in[0];
    const float* hidden = (const float*)d_in[1];
    const float* emb    = (const float*)d_in[2];
    const float* We     = (const float*)d_in[3];
    const float* Wh     = (const float*)d_in[4];
    const float* Wo     = (const float*)d_in[5];
    float* out = (float*)d_out;

    prep_kernel<<<VOCAB, H>>>(emb, We);
    rnn_kernel<<<BATCH / NROW, NTHR>>>(x, hidden, Wh, Wo, out, out_size);
}

// round 8
// speedup vs baseline: 1.1076x; 1.1076x over previous
#include <cuda_runtime.h>

// CharRNN on GB300 — R7.
// Insight from R5/R6 ncu: shared-mem pipe cost = register-delivered bytes
// (128 B/cyc/SM, broadcast does NOT dedup). h-bytes/step = 320KB / cols_per_thread.
// => raise cols_per_thread to 5 (was 1): matvec LDS 2500 -> ~500 cyc/step.
//  - 128 CTAs x 320 threads; thread (jg, kc): 5 output cols, K-chunk of 25, both rows.
//  - W_h slice in regs (125 floats, 13 f32x2 pairs/col; tail pair has w.y=0 vs
//    zero-initialized smem pad), W_o slice (26 floats) for fused logits that
//    reuse the register h chunk -> zero extra LDS for logits.
//  - Reduction over 8 K-chunks via smem partials pmat[r][col][12-pad], 2 bar/step.

#define H     200
#define NROW  2
#define SEQ   1024
#define VOCAB 33
#define BATCH 256
#define KC    8            // K chunks
#define KPT   25           // K per chunk
#define CPAD  28           // padded chunk stride in hbuf (floats)
#define CP    5            // output columns per thread
#define PST   12           // pmat kc-stride (padded, 48B -> aligned float4 reads)
#define NTHR  320

__device__ float g_EWe[VOCAB * H];

union U64 { unsigned long long u; float2 f; };

__device__ __forceinline__ void ffma2(U64 &acc, U64 a, U64 b) {
    asm("fma.rn.f32x2 %0, %1, %2, %0;" : "+l"(acc.u) : "l"(a.u), "l"(b.u));
}
__device__ __forceinline__ float fast_tanh(float v) {
    v = fminf(15.f, fmaxf(-15.f, v));
    float e = __expf(2.f * v);
    return __fdividef(e - 1.f, e + 1.f);
}

__global__ void prep_kernel(const float* __restrict__ emb,
                            const float* __restrict__ We) {
    int v = blockIdx.x;
    int j = threadIdx.x;
    float acc = 0.f;
    #pragma unroll 4
    for (int e = 0; e < H; e++)
        acc = fmaf(emb[v * H + e], We[e * H + j], acc);
    g_EWe[v * H + j] = acc;
}

__global__ void __launch_bounds__(NTHR, 1) rnn_kernel(
    const int* __restrict__ x, const float* __restrict__ h0,
    const float* __restrict__ Wh, const float* __restrict__ Wo,
    float* __restrict__ out, int out_elems)
{
    __shared__ float hbuf[2][NROW][KC * CPAD];   // chunk-padded hidden, dbl-buf
    __shared__ float pmat[NROW][H][PST];         // matvec partials [r][col][kc]
    __shared__ float lpart[VOCAB][NROW][KC];     // logits partials
    __shared__ int   tok[NROW][SEQ];

    const int tid = threadIdx.x;
    const int b0  = blockIdx.x * NROW;
    const int jg  = tid >> 3;       // col group 0..39
    const int kc  = tid & 7;        // K-chunk 0..7

    // ---- init: hbuf (h0 + zero pads, single pass = no race), tokens ----
    for (int idx = tid; idx < 2 * NROW * KC * CPAD; idx += NTHR) {
        int buf = idx / (NROW * KC * CPAD);
        int rem = idx - buf * (NROW * KC * CPAD);
        int r   = rem / (KC * CPAD);
        int cc  = rem - r * (KC * CPAD);
        int ch  = cc / CPAD, off = cc - ch * CPAD;
        float v = 0.f;
        if (buf == 0 && off < KPT)
            v = h0[(b0 + r) * H + ch * KPT + off];
        (&hbuf[0][0][0])[idx] = v;
    }
    for (int idx = tid; idx < NROW * SEQ; idx += NTHR) {
        int r = idx >> 10, t = idx & (SEQ - 1);
        tok[r][t] = x[(b0 + r) * SEQ + t];
    }

    // ---- W_h slice -> registers: 13 pairs per col (tail pair y = 0) ----
    U64 wp[CP][13];
    #pragma unroll
    for (int c = 0; c < CP; c++) {
        int j = jg * CP + c;
        #pragma unroll
        for (int m = 0; m < 12; m++) {
            int k0 = kc * KPT + 2 * m;
            wp[c][m].f = make_float2(Wh[k0 * H + j], Wh[(k0 + 1) * H + j]);
        }
        wp[c][12].f = make_float2(Wh[(kc * KPT + 24) * H + j], 0.f);
    }
    // ---- W_o slice for fused logits (threads with jg < VOCAB) ----
    const bool do_log = (jg < VOCAB);
    U64 wop[13];
    if (do_log) {
        #pragma unroll
        for (int m = 0; m < 12; m++) {
            int k0 = kc * KPT + 2 * m;
            wop[m].f = make_float2(Wo[k0 * VOCAB + jg], Wo[(k0 + 1) * VOCAB + jg]);
        }
        wop[12].f = make_float2(Wo[(kc * KPT + 24) * VOCAB + jg], 0.f);
    }

    // ---- phase-2 output assignments ----
    const int  o1 = tid;                   // outputs 0..319
    const int  r1 = o1 / H, c1 = o1 - r1 * H;
    const int  w1 = (c1 / KPT) * CPAD + (c1 % KPT);
    const bool has2 = (tid < NROW * H - NTHR);   // 80 threads: outputs 320..399
    const int  o2 = tid + NTHR;
    const int  r2 = o2 / H, c2 = o2 - r2 * H;
    const int  w2 = (c2 / KPT) * CPAD + (c2 % KPT);

    __syncthreads();

    int cur = 0;
    for (int t = 0; t < SEQ; t++) {
        // xw prefetch for this thread's phase-2 outputs (L1-resident table)
        float xw1 = g_EWe[tok[r1][t] * H + c1];
        float xw2 = 0.f;
        if (has2) xw2 = g_EWe[tok[r2][t] * H + c2];

        // ---- phase 1: matvec + fused logits partials ----
        const float4* h0p = (const float4*)&hbuf[cur][0][kc * CPAD];
        const float4* h1p = (const float4*)&hbuf[cur][1][kc * CPAD];
        U64 acc[CP][2];
        #pragma unroll
        for (int c = 0; c < CP; c++) { acc[c][0].u = 0ull; acc[c][1].u = 0ull; }
        U64 l0, l1; l0.u = l1.u = 0ull;

        #pragma unroll
        for (int m4 = 0; m4 < 6; m4++) {
            float4 v0 = h0p[m4];
            float4 v1 = h1p[m4];
            U64 p00, p01, p10, p11;
            p00.f = make_float2(v0.x, v0.y);
            p01.f = make_float2(v0.z, v0.w);
            p10.f = make_float2(v1.x, v1.y);
            p11.f = make_float2(v1.z, v1.w);
            #pragma unroll
            for (int c = 0; c < CP; c++) {
                ffma2(acc[c][0], p00, wp[c][2 * m4]);
                ffma2(acc[c][0], p01, wp[c][2 * m4 + 1]);
                ffma2(acc[c][1], p10, wp[c][2 * m4]);
                ffma2(acc[c][1], p11, wp[c][2 * m4 + 1]);
            }
            if (do_log) {
                ffma2(l0, p00, wop[2 * m4]);
                ffma2(l0, p01, wop[2 * m4 + 1]);
                ffma2(l1, p10, wop[2 * m4]);
                ffma2(l1, p11, wop[2 * m4 + 1]);
            }
        }
        {   // K tail: element 24 (+pad 25 = 0 against w.y = 0)
            U64 t0, t1;
            t0.f = *(const float2*)&hbuf[cur][0][kc * CPAD + 24];
            t1.f = *(const float2*)&hbuf[cur][1][kc * CPAD + 24];
            #pragma unroll
            for (int c = 0; c < CP; c++) {
                ffma2(acc[c][0], t0, wp[c][12]);
                ffma2(acc[c][1], t1, wp[c][12]);
            }
            if (do_log) { ffma2(l0, t0, wop[12]); ffma2(l1, t1, wop[12]); }
        }

        #pragma unroll
        for (int c = 0; c < CP; c++) {
            pmat[0][jg * CP + c][kc] = acc[c][0].f.x + acc[c][0].f.y;
            pmat[1][jg * CP + c][kc] = acc[c][1].f.x + acc[c][1].f.y;
        }
        if (do_log) {
            lpart[jg][0][kc] = l0.f.x + l0.f.y;
            lpart[jg][1][kc] = l1.f.x + l1.f.y;
        }
        __syncthreads();

        // ---- phase 2: reduce + tanh + h write + deferred logits store ----
        const int nxt = cur ^ 1;
        {
            float4 s0 = *(const float4*)&pmat[r1][c1][0];
            float4 s1 = *(const float4*)&pmat[r1][c1][4];
            float y = ((s0.x + s0.y) + (s0.z + s0.w))
                    + ((s1.x + s1.y) + (s1.z + s1.w));
            hbuf[nxt][r1][w1] = fast_tanh(xw1 + y);
        }
        if (has2) {
            float4 s0 = *(const float4*)&pmat[r2][c2][0];
            float4 s1 = *(const float4*)&pmat[r2][c2][4];
            float y = ((s0.x + s0.y) + (s0.z + s0.w))
                    + ((s1.x + s1.y) + (s1.z + s1.w));
            hbuf[nxt][r2][w2] = fast_tanh(xw2 + y);
        }
        if (t && tid < NROW * VOCAB) {        // logits for h_{t-1}
            int r = tid & 1, v = tid >> 1;
            float4 a = *(const float4*)&lpart[v][r][0];
            float4 b = *(const float4*)&lpart[v][r][4];
            out[((long long)(b0 + r) * SEQ + (t - 1)) * VOCAB + v]
                = ((a.x + a.y) + (a.z + a.w)) + ((b.x + b.y) + (b.z + b.w));
        }
        __syncthreads();
        cur = nxt;
    }

    // ---- epilogue: logits for h_{SEQ-1} ----
    if (do_log) {
        const float4* h0p = (const float4*)&hbuf[cur][0][kc * CPAD];
        const float4* h1p = (const float4*)&hbuf[cur][1][kc * CPAD];
        U64 l0, l1; l0.u = l1.u = 0ull;
        #pragma unroll
        for (int m4 = 0; m4 < 6; m4++) {
            float4 v0 = h0p[m4];
            float4 v1 = h1p[m4];
            U64 p00, p01, p10, p11;
            p00.f = make_float2(v0.x, v0.y);
            p01.f = make_float2(v0.z, v0.w);
            p10.f = make_float2(v1.x, v1.y);
            p11.f = make_float2(v1.z, v1.w);
            ffma2(l0, p00, wop[2 * m4]);
            ffma2(l0, p01, wop[2 * m4 + 1]);
            ffma2(l1, p10, wop[2 * m4]);
            ffma2(l1, p11, wop[2 * m4 + 1]);
        }
        U64 t0, t1;
        t0.f = *(const float2*)&hbuf[cur][0][kc * CPAD + 24];
        t1.f = *(const float2*)&hbuf[cur][1][kc * CPAD + 24];
        ffma2(l0, t0, wop[12]);
        ffma2(l1, t1, wop[12]);
        lpart[jg][0][kc] = l0.f.x + l0.f.y;
        lpart[jg][1][kc] = l1.f.x + l1.f.y;
    }
    __syncthreads();
    if (tid < NROW * VOCAB) {
        int r = tid & 1, v = tid >> 1;
        float4 a = *(const float4*)&lpart[v][r][0];
        float4 b = *(const float4*)&lpart[v][r][4];
        out[((long long)(b0 + r) * SEQ + (SEQ - 1)) * VOCAB + v]
            = ((a.x + a.y) + (a.z + a.w)) + ((b.x + b.y) + (b.z + b.w));
    }

    // ---- final hidden (second output, if present in d_out) ----
    long long base = (long long)BATCH * SEQ * VOCAB;
    if ((long long)out_elems >= base + (long long)BATCH * H) {
        for (int idx = tid; idx < NROW * H; idx += NTHR) {
            int r = idx / H, jj = idx - r * H;
            out[base + (long long)(b0 + r) * H + jj]
                = hbuf[cur][r][(jj / KPT) * CPAD + (jj % KPT)];
        }
    }
}

extern "C" void kernel_launch(void* const* d_in, const int* in_sizes, int n_in,
                              void* d_out, int out_size) {
    // metadata order: x(int32), hidden, embedding, W_e, W_h, W_o
    const int*   x      = (const int*)d_in[0];
    const float* hidden = (const float*)d_in[1];
    const float* emb    = (const float*)d_in[2];
    const float* We     = (const float*)d_in[3];
    const float* Wh     = (const float*)d_in[4];
    const float* Wo     = (const float*)d_in[5];
    float* out = (float*)d_out;

    prep_kernel<<<VOCAB, H>>>(emb, We);
    rnn_kernel<<<BATCH / NROW, NTHR>>>(x, hidden, Wh, Wo, out, out_size);
}

// round 12
// speedup vs baseline: 1.6152x; 1.4583x over previous
#include <cuda_runtime.h>

// CharRNN on GB300 — R9.
// R7 post-mortem: L2=15.7% with all data nominally on-chip => register spills
// (wp+wop+acc ~185 regs > the 168 allocated). Fix: W_o slice moved to smem,
// W_h K-tail made scalar => ~190 regs, spill-free at 320thr (limit 204).
// Also: single barrier per step. K-chunk kc lives in lane bits 0-2, so the
// 8-chunk reduction is an in-warp shfl_xor butterfly (pmat smem round-trip and
// the second __syncthreads are gone). WoS padded to 40 groups => branch-free
// inner loop (no divergence around inline-asm FFMA2).

#define H     200
#define NROW  2
#define SEQ   1024
#define VOCAB 33
#define BATCH 256
#define KC    8
#define KPT   25
#define CPAD  28           // padded chunk stride in hbuf (floats)
#define CP    5
#define NG    40           // col groups (jg), padded past VOCAB for logits
#define NTHR  320

__device__ float g_EWe[VOCAB * H];

union U64 { unsigned long long u; float2 f; };

__device__ __forceinline__ void ffma2(U64 &acc, U64 a, U64 b) {
    asm("fma.rn.f32x2 %0, %1, %2, %0;" : "+l"(acc.u) : "l"(a.u), "l"(b.u));
}
__device__ __forceinline__ float fast_tanh(float v) {
    v = fminf(15.f, fmaxf(-15.f, v));
    float e = __expf(2.f * v);
    return __fdividef(e - 1.f, e + 1.f);
}

__global__ void prep_kernel(const float* __restrict__ emb,
                            const float* __restrict__ We) {
    int v = blockIdx.x;
    int j = threadIdx.x;
    float acc = 0.f;
    #pragma unroll 4
    for (int e = 0; e < H; e++)
        acc = fmaf(emb[v * H + e], We[e * H + j], acc);
    g_EWe[v * H + j] = acc;
}

__global__ void __launch_bounds__(NTHR, 1) rnn_kernel(
    const int* __restrict__ x, const float* __restrict__ h0,
    const float* __restrict__ Wh, const float* __restrict__ Wo,
    float* __restrict__ out, int out_elems)
{
    __shared__ float  hbuf[2][NROW][KC * CPAD];  // chunk-padded h, double-buffered
    __shared__ int    tok[NROW][SEQ];
    __shared__ float2 WoS[NG][KC][13];           // W_o^T slices (zero-padded jg>=33)

    const int tid  = threadIdx.x;
    const int lane = tid & 31;
    const int warp = tid >> 5;
    const int kc   = lane & 7;          // K-chunk, lane bits 0-2 (shfl group)
    const int sub  = lane >> 3;         // col-subgroup within warp
    const int jg   = warp * 4 + sub;    // col group 0..39
    const int b0   = blockIdx.x * NROW;

    // ---- init hbuf (both buffers, zero pads), tokens, WoS ----
    for (int idx = tid; idx < 2 * NROW * KC * CPAD; idx += NTHR) {
        int buf = idx / (NROW * KC * CPAD);
        int rem = idx - buf * (NROW * KC * CPAD);
        int r   = rem / (KC * CPAD);
        int cc  = rem - r * (KC * CPAD);
        int ch  = cc / CPAD, off = cc - ch * CPAD;
        float v = 0.f;
        if (buf == 0 && off < KPT) v = h0[(b0 + r) * H + ch * KPT + off];
        (&hbuf[0][0][0])[idx] = v;
    }
    for (int idx = tid; idx < NROW * SEQ; idx += NTHR) {
        int r = idx >> 10, t = idx & (SEQ - 1);
        tok[r][t] = x[(b0 + r) * SEQ + t];
    }
    for (int idx = tid; idx < NG * KC * 13; idx += NTHR) {
        int v = idx / (KC * 13);
        int rem = idx - v * (KC * 13);
        int k = rem / 13, m = rem - k * 13;
        float a = 0.f, b = 0.f;
        if (v < VOCAB) {
            int k0 = k * KPT + 2 * m;
            a = Wo[k0 * VOCAB + v];
            if (2 * m + 1 < KPT) b = Wo[(k0 + 1) * VOCAB + v];
        }
        WoS[v][k][m] = make_float2(a, b);
    }

    // ---- W_h slice -> registers: 12 pairs + scalar tail per column ----
    U64 wp[CP][12];
    float w24[CP];
    #pragma unroll
    for (int c = 0; c < CP; c++) {
        int j = jg * CP + c;
        #pragma unroll
        for (int m = 0; m < 12; m++) {
            int k0 = kc * KPT + 2 * m;
            wp[c][m].f = make_float2(Wh[k0 * H + j], Wh[(k0 + 1) * H + j]);
        }
        w24[c] = Wh[(kc * KPT + 24) * H + j];
    }

    // ---- h-writer assignment: value v = c*2+r; lane kc writes v=kc,
    //      lanes 0,1 additionally write v=8+kc ----
    const int  c1 = kc >> 1, r1 = kc & 1;
    const int  j1 = jg * CP + c1;
    const int  w1 = (j1 / KPT) * CPAD + (j1 % KPT);
    const bool has2 = (kc < 2);
    const int  r2 = kc;                       // c2 = 4
    const int  j2 = jg * CP + 4;
    const int  w2 = (j2 / KPT) * CPAD + (j2 % KPT);

    const bool log_store = (jg < VOCAB) && (kc < 2);

    __syncthreads();

    int cur = 0;
    for (int t = 0; t < SEQ; t++) {
        // xw prefetch (L1-resident table) — overlaps the FFMA block
        float xw1 = g_EWe[tok[r1][t] * H + j1];
        float xw2 = has2 ? g_EWe[tok[r2][t] * H + j2] : 0.f;

        // ---- matvec + logits partials (branch-free) ----
        const float4* a0 = (const float4*)&hbuf[cur][0][kc * CPAD];
        const float4* a1 = (const float4*)&hbuf[cur][1][kc * CPAD];
        const float2* wo = &WoS[jg][kc][0];
        U64 acc[CP][2];
        #pragma unroll
        for (int c = 0; c < CP; c++) { acc[c][0].u = 0ull; acc[c][1].u = 0ull; }
        U64 l0, l1; l0.u = l1.u = 0ull;

        #pragma unroll
        for (int m4 = 0; m4 < 6; m4++) {
            float4 v0 = a0[m4];
            float4 v1 = a1[m4];
            U64 p00, p01, p10, p11;
            p00.f = make_float2(v0.x, v0.y);
            p01.f = make_float2(v0.z, v0.w);
            p10.f = make_float2(v1.x, v1.y);
            p11.f = make_float2(v1.z, v1.w);
            #pragma unroll
            for (int c = 0; c < CP; c++) {
                ffma2(acc[c][0], p00, wp[c][2 * m4]);
                ffma2(acc[c][0], p01, wp[c][2 * m4 + 1]);
                ffma2(acc[c][1], p10, wp[c][2 * m4]);
                ffma2(acc[c][1], p11, wp[c][2 * m4 + 1]);
            }
            U64 wv0, wv1;
            wv0.f = wo[2 * m4];
            wv1.f = wo[2 * m4 + 1];
            ffma2(l0, p00, wv0);
            ffma2(l0, p01, wv1);
            ffma2(l1, p10, wv0);
            ffma2(l1, p11, wv1);
        }
        // K tail (element 24), scalar
        float h0t = hbuf[cur][0][kc * CPAD + 24];
        float h1t = hbuf[cur][1][kc * CPAD + 24];
        float wo24 = wo[12].x;

        float y[CP][2];
        #pragma unroll
        for (int c = 0; c < CP; c++) {
            y[c][0] = (acc[c][0].f.x + acc[c][0].f.y) + h0t * w24[c];
            y[c][1] = (acc[c][1].f.x + acc[c][1].f.y) + h1t * w24[c];
        }
        float L0 = (l0.f.x + l0.f.y) + h0t * wo24;
        float L1 = (l1.f.x + l1.f.y) + h1t * wo24;

        // ---- in-warp butterfly over the 8 K-chunks (lane bits 0-2) ----
        #pragma unroll
        for (int d = 1; d < 8; d <<= 1) {
            #pragma unroll
            for (int c = 0; c < CP; c++) {
                y[c][0] += __shfl_xor_sync(0xFFFFFFFFu, y[c][0], d);
                y[c][1] += __shfl_xor_sync(0xFFFFFFFFu, y[c][1], d);
            }
            L0 += __shfl_xor_sync(0xFFFFFFFFu, L0, d);
            L1 += __shfl_xor_sync(0xFFFFFFFFu, L1, d);
        }

        // logits store for h_{t-1} (position t-1)
        if (t && log_store) {
            float L = kc ? L1 : L0;
            out[((long long)(b0 + kc) * SEQ + (t - 1)) * VOCAB + jg] = L;
        }

        // ---- tanh + h write (all sums present in every lane; SEL by kc) ----
        const int nxt = cur ^ 1;
        {
            float yr0 = (c1 == 0) ? y[0][0] : (c1 == 1) ? y[1][0]
                       : (c1 == 2) ? y[2][0] : y[3][0];
            float yr1 = (c1 == 0) ? y[0][1] : (c1 == 1) ? y[1][1]
                       : (c1 == 2) ? y[2][1] : y[3][1];
            float yv = r1 ? yr1 : yr0;
            hbuf[nxt][r1][w1] = fast_tanh(xw1 + yv);
        }
        if (has2) {
            float yv = r2 ? y[4][1] : y[4][0];
            hbuf[nxt][r2][w2] = fast_tanh(xw2 + yv);
        }
        __syncthreads();
        cur = nxt;
    }

    // ---- epilogue: logits for h_{SEQ-1} ----
    {
        const float4* a0 = (const float4*)&hbuf[cur][0][kc * CPAD];
        const float4* a1 = (const float4*)&hbuf[cur][1][kc * CPAD];
        const float2* wo = &WoS[jg][kc][0];
        U64 l0, l1; l0.u = l1.u = 0ull;
        #pragma unroll
        for (int m4 = 0; m4 < 6; m4++) {
            float4 v0 = a0[m4];
            float4 v1 = a1[m4];
            U64 p00, p01, p10, p11;
            p00.f = make_float2(v0.x, v0.y);
            p01.f = make_float2(v0.z, v0.w);
            p10.f = make_float2(v1.x, v1.y);
            p11.f = make_float2(v1.z, v1.w);
            U64 wv0, wv1;
            wv0.f = wo[2 * m4];
            wv1.f = wo[2 * m4 + 1];
            ffma2(l0, p00, wv0);
            ffma2(l0, p01, wv1);
            ffma2(l1, p10, wv0);
            ffma2(l1, p11, wv1);
        }
        float h0t = hbuf[cur][0][kc * CPAD + 24];
        float h1t = hbuf[cur][1][kc * CPAD + 24];
        float wo24 = wo[12].x;
        float L0 = (l0.f.x + l0.f.y) + h0t * wo24;
        float L1 = (l1.f.x + l1.f.y) + h1t * wo24;
        #pragma unroll
        for (int d = 1; d < 8; d <<= 1) {
            L0 += __shfl_xor_sync(0xFFFFFFFFu, L0, d);
            L1 += __shfl_xor_sync(0xFFFFFFFFu, L1, d);
        }
        if (log_store) {
            float L = kc ? L1 : L0;
            out[((long long)(b0 + kc) * SEQ + (SEQ - 1)) * VOCAB + jg] = L;
        }
    }

    // ---- final hidden (second output, if present in d_out) ----
    long long base = (long long)BATCH * SEQ * VOCAB;
    if ((long long)out_elems >= base + (long long)BATCH * H) {
        for (int idx = tid; idx < NROW * H; idx += NTHR) {
            int r = idx / H, jj = idx - r * H;
            out[base + (long long)(b0 + r) * H + jj]
                = hbuf[cur][r][(jj / KPT) * CPAD + (jj % KPT)];
        }
    }
}

extern "C" void kernel_launch(void* const* d_in, const int* in_sizes, int n_in,
                              void* d_out, int out_size) {
    // metadata order: x(int32), hidden, embedding, W_e, W_h, W_o
    const int*   x      = (const int*)d_in[0];
    const float* hidden = (const float*)d_in[1];
    const float* emb    = (const float*)d_in[2];
    const float* We     = (const float*)d_in[3];
    const float* Wh     = (const float*)d_in[4];
    const float* Wo     = (const float*)d_in[5];
    float* out = (float*)d_out;

    prep_kernel<<<VOCAB, H>>>(emb, We);
    rnn_kernel<<<BATCH / NROW, NTHR>>>(x, hidden, Wh, Wo, out, out_size);
}

// round 15
// speedup vs baseline: 2.0085x; 1.2435x over previous
#include <cuda_runtime.h>

// CharRNN on GB300 — R13.
// R12 derived ~371 inst/thread-step vs ~230 hand-counted: repack MOVs for the
// 64-bit FFMA2 operands + 36-shfl butterfly. Fixes:
//  (1) LDS as ulonglong2 / u64: loaded bits ARE the f32x2 operands, no cracking.
//  (2) reduce-scatter (16 padded slots, 14 shfl + SELs) replaces the butterfly;
//      lane kc ends owning values {2kc,2kc+1} => writer logic is trivial:
//      lane kc<5 owns column jg*5+kc (both rows), lane kc==5 owns both logits.

#define H     200
#define NROW  2
#define SEQ   1024
#define VOCAB 33
#define BATCH 256
#define KC    8
#define KPT   25
#define CPAD  28           // padded chunk stride in hbuf (floats); 112B, 16B-aligned
#define CP    5
#define NG    40           // col groups (jg), zero-padded past VOCAB
#define NTHR  320

__device__ float g_EWe[VOCAB * H];

union U64 { unsigned long long u; float2 f; };

__device__ __forceinline__ void ffma2(U64 &acc, U64 a, U64 b) {
    asm("fma.rn.f32x2 %0, %1, %2, %0;" : "+l"(acc.u) : "l"(a.u), "l"(b.u));
}
__device__ __forceinline__ float fast_tanh(float v) {
    v = fminf(15.f, fmaxf(-15.f, v));
    float e = __expf(2.f * v);
    return __fdividef(e - 1.f, e + 1.f);
}

__global__ void prep_kernel(const float* __restrict__ emb,
                            const float* __restrict__ We) {
    int v = blockIdx.x;
    int j = threadIdx.x;
    float acc = 0.f;
    #pragma unroll 4
    for (int e = 0; e < H; e++)
        acc = fmaf(emb[v * H + e], We[e * H + j], acc);
    g_EWe[v * H + j] = acc;
}

__global__ void __launch_bounds__(NTHR, 1) rnn_kernel(
    const int* __restrict__ x, const float* __restrict__ h0,
    const float* __restrict__ Wh, const float* __restrict__ Wo,
    float* __restrict__ out, int out_elems)
{
    __shared__ float  hbuf[2][NROW][KC * CPAD];
    __shared__ int    tok[NROW][SEQ];
    __shared__ float2 WoS[NG][KC][13];

    const int tid  = threadIdx.x;
    const int lane = tid & 31;
    const int warp = tid >> 5;
    const int kc   = lane & 7;          // K-chunk, lane bits 0-2
    const int sub  = lane >> 3;
    const int jg   = warp * 4 + sub;    // col group 0..39
    const int b0   = blockIdx.x * NROW;

    // ---- init hbuf (both buffers, zero pads), tokens, WoS ----
    for (int idx = tid; idx < 2 * NROW * KC * CPAD; idx += NTHR) {
        int buf = idx / (NROW * KC * CPAD);
        int rem = idx - buf * (NROW * KC * CPAD);
        int r   = rem / (KC * CPAD);
        int cc  = rem - r * (KC * CPAD);
        int ch  = cc / CPAD, off = cc - ch * CPAD;
        float v = 0.f;
        if (buf == 0 && off < KPT) v = h0[(b0 + r) * H + ch * KPT + off];
        (&hbuf[0][0][0])[idx] = v;
    }
    for (int idx = tid; idx < NROW * SEQ; idx += NTHR) {
        int r = idx >> 10, t = idx & (SEQ - 1);
        tok[r][t] = x[(b0 + r) * SEQ + t];
    }
    for (int idx = tid; idx < NG * KC * 13; idx += NTHR) {
        int v = idx / (KC * 13);
        int rem = idx - v * (KC * 13);
        int k = rem / 13, m = rem - k * 13;
        float a = 0.f, b = 0.f;
        if (v < VOCAB) {
            int k0 = k * KPT + 2 * m;
            a = Wo[k0 * VOCAB + v];
            if (2 * m + 1 < KPT) b = Wo[(k0 + 1) * VOCAB + v];
        }
        WoS[v][k][m] = make_float2(a, b);
    }

    // ---- W_h slice -> registers: 12 pairs + scalar tail per column ----
    U64 wp[CP][12];
    float w24[CP];
    #pragma unroll
    for (int c = 0; c < CP; c++) {
        int j = jg * CP + c;
        #pragma unroll
        for (int m = 0; m < 12; m++) {
            int k0 = kc * KPT + 2 * m;
            wp[c][m].f = make_float2(Wh[k0 * H + j], Wh[(k0 + 1) * H + j]);
        }
        w24[c] = Wh[(kc * KPT + 24) * H + j];
    }

    // ---- ownership after reduce-scatter: lane kc holds values {2kc, 2kc+1} ----
    const bool own = (kc < CP);                 // h writer: column jg*CP+kc, rows 0,1
    const int  jmy = jg * CP + (own ? kc : 0);
    const int  wmy = (jmy / KPT) * CPAD + (jmy % KPT);
    const bool log_lane = (kc == 5) && (jg < VOCAB);

    __syncthreads();

    int cur = 0;
    for (int t = 0; t < SEQ; t++) {
        // xw prefetch (L1-resident table), only the lanes that will use it
        float xw0 = 0.f, xw1 = 0.f;
        if (own) {
            xw0 = g_EWe[tok[0][t] * H + jmy];
            xw1 = g_EWe[tok[1][t] * H + jmy];
        }

        // ---- matvec + logits partials (branch-free) ----
        const ulonglong2* a0 = (const ulonglong2*)&hbuf[cur][0][kc * CPAD];
        const ulonglong2* a1 = (const ulonglong2*)&hbuf[cur][1][kc * CPAD];
        const float2* wo = &WoS[jg][kc][0];
        U64 acc[CP][2];
        #pragma unroll
        for (int c = 0; c < CP; c++) { acc[c][0].u = 0ull; acc[c][1].u = 0ull; }
        U64 l0, l1; l0.u = l1.u = 0ull;

        #pragma unroll
        for (int m4 = 0; m4 < 6; m4++) {
            ulonglong2 q0 = a0[m4];      // LDS.128: two ready f32x2 operands
            ulonglong2 q1 = a1[m4];
            U64 p00, p01, p10, p11;
            p00.u = q0.x; p01.u = q0.y;
            p10.u = q1.x; p11.u = q1.y;
            #pragma unroll
            for (int c = 0; c < CP; c++) {
                ffma2(acc[c][0], p00, wp[c][2 * m4]);
                ffma2(acc[c][0], p01, wp[c][2 * m4 + 1]);
                ffma2(acc[c][1], p10, wp[c][2 * m4]);
                ffma2(acc[c][1], p11, wp[c][2 * m4 + 1]);
            }
            U64 wv0, wv1;
            wv0.u = *(const unsigned long long*)&wo[2 * m4];
            wv1.u = *(const unsigned long long*)&wo[2 * m4 + 1];
            ffma2(l0, p00, wv0);
            ffma2(l0, p01, wv1);
            ffma2(l1, p10, wv0);
            ffma2(l1, p11, wv1);
        }
        // K tail (element 24), scalar
        float h0t  = hbuf[cur][0][kc * CPAD + 24];
        float h1t  = hbuf[cur][1][kc * CPAD + 24];
        float wo24 = wo[12].x;

        // ---- 16 reduction slots: s[2c+r]=y, s[10]=L0, s[11]=L1, rest pad ----
        float s[16];
        #pragma unroll
        for (int c = 0; c < CP; c++) {
            s[2 * c]     = (acc[c][0].f.x + acc[c][0].f.y) + h0t * w24[c];
            s[2 * c + 1] = (acc[c][1].f.x + acc[c][1].f.y) + h1t * w24[c];
        }
        s[10] = (l0.f.x + l0.f.y) + h0t * wo24;
        s[11] = (l1.f.x + l1.f.y) + h1t * wo24;
        s[12] = s[13] = s[14] = s[15] = 0.f;

        // ---- reduce-scatter over kc bits: 14 shfl total ----
        #pragma unroll
        for (int i = 0; i < 8; i++) {
            float snd = (kc & 4) ? s[i] : s[i + 8];
            float rcv = __shfl_xor_sync(0xFFFFFFFFu, snd, 4);
            s[i] = ((kc & 4) ? s[i + 8] : s[i]) + rcv;
        }
        #pragma unroll
        for (int i = 0; i < 4; i++) {
            float snd = (kc & 2) ? s[i] : s[i + 4];
            float rcv = __shfl_xor_sync(0xFFFFFFFFu, snd, 2);
            s[i] = ((kc & 2) ? s[i + 4] : s[i]) + rcv;
        }
        #pragma unroll
        for (int i = 0; i < 2; i++) {
            float snd = (kc & 1) ? s[i] : s[i + 2];
            float rcv = __shfl_xor_sync(0xFFFFFFFFu, snd, 1);
            s[i] = ((kc & 1) ? s[i + 2] : s[i]) + rcv;
        }
        // lane kc: s[0]=value 2kc, s[1]=value 2kc+1
        //   kc<5 : (y_row0, y_row1) for column jmy
        //   kc==5: (L0, L1) for vocab jg

        if (t && log_lane) {
            out[((long long)(b0 + 0) * SEQ + (t - 1)) * VOCAB + jg] = s[0];
            out[((long long)(b0 + 1) * SEQ + (t - 1)) * VOCAB + jg] = s[1];
        }

        const int nxt = cur ^ 1;
        if (own) {
            hbuf[nxt][0][wmy] = fast_tanh(xw0 + s[0]);
            hbuf[nxt][1][wmy] = fast_tanh(xw1 + s[1]);
        }
        __syncthreads();
        cur = nxt;
    }

    // ---- epilogue: logits for h_{SEQ-1} (butterfly, once) ----
    {
        const ulonglong2* a0 = (const ulonglong2*)&hbuf[cur][0][kc * CPAD];
        const ulonglong2* a1 = (const ulonglong2*)&hbuf[cur][1][kc * CPAD];
        const float2* wo = &WoS[jg][kc][0];
        U64 l0, l1; l0.u = l1.u = 0ull;
        #pragma unroll
        for (int m4 = 0; m4 < 6; m4++) {
            ulonglong2 q0 = a0[m4];
            ulonglong2 q1 = a1[m4];
            U64 p00, p01, p10, p11;
            p00.u = q0.x; p01.u = q0.y;
            p10.u = q1.x; p11.u = q1.y;
            U64 wv0, wv1;
            wv0.u = *(const unsigned long long*)&wo[2 * m4];
            wv1.u = *(const unsigned long long*)&wo[2 * m4 + 1];
            ffma2(l0, p00, wv0);
            ffma2(l0, p01, wv1);
            ffma2(l1, p10, wv0);
            ffma2(l1, p11, wv1);
        }
        float h0t  = hbuf[cur][0][kc * CPAD + 24];
        float h1t  = hbuf[cur][1][kc * CPAD + 24];
        float wo24 = wo[12].x;
        float L0 = (l0.f.x + l0.f.y) + h0t * wo24;
        float L1 = (l1.f.x + l1.f.y) + h1t * wo24;
        #pragma unroll
        for (int d = 1; d < 8; d <<= 1) {
            L0 += __shfl_xor_sync(0xFFFFFFFFu, L0, d);
            L1 += __shfl_xor_sync(0xFFFFFFFFu, L1, d);
        }
        if (log_lane) {
            out[((long long)(b0 + 0) * SEQ + (SEQ - 1)) * VOCAB + jg] = L0;
            out[((long long)(b0 + 1) * SEQ + (SEQ - 1)) * VOCAB + jg] = L1;
        }
    }

    // ---- final hidden (second output, if present in d_out) ----
    long long base = (long long)BATCH * SEQ * VOCAB;
    if ((long long)out_elems >= base + (long long)BATCH * H) {
        for (int idx = tid; idx < NROW * H; idx += NTHR) {
            int r = idx / H, jj = idx - r * H;
            out[base + (long long)(b0 + r) * H + jj]
                = hbuf[cur][r][(jj / KPT) * CPAD + (jj % KPT)];
        }
    }
}

extern "C" void kernel_launch(void* const* d_in, const int* in_sizes, int n_in,
                              void* d_out, int out_size) {
    // metadata order: x(int32), hidden, embedding, W_e, W_h, W_o
    const int*   x      = (const int*)d_in[0];
    const float* hidden = (const float*)d_in[1];
    const float* emb    = (const float*)d_in[2];
    const float* We     = (const float*)d_in[3];
    const float* Wh     = (const float*)d_in[4];
    const float* Wo     = (const float*)d_in[5];
    float* out = (float*)d_out;

    prep_kernel<<<VOCAB, H>>>(emb, We);
    rnn_kernel<<<BATCH / NROW, NTHR>>>(x, hidden, Wh, Wo, out, out_size);
}